// round 1
// baseline (speedup 1.0000x reference)
#include <cuda_runtime.h>

#define SEQ     4096
#define DMODEL  1024
#define NH      16
#define HDIM    64
#define KVS     68   // Ks/Vs row stride (floats): 68%32=4 -> consecutive rows hit distinct bank quads
#define PSS     65   // Ps row stride

// Scratch: Q, K, V, AttnOut  (4 x 16 MB fp32)
__device__ float g_scratch[4ull * SEQ * DMODEL];

// ---------------- GEMM: C[M,N] = A[M,K] @ W[K,N] + bias[N] ----------------
__global__ __launch_bounds__(256) void gemm_bias_kernel(
    const float* __restrict__ A, const float* __restrict__ W,
    const float* __restrict__ bias, float* __restrict__ C,
    int M, int N, int K)
{
    __shared__ float As[16][64];   // transposed: As[k][m]
    __shared__ float Bs[16][64];   // Bs[k][n]
    const int tid = threadIdx.x;
    const int n0 = blockIdx.x * 64;
    const int m0 = blockIdx.y * 64;
    const int tx = tid & 15;
    const int ty = tid >> 4;

    const int ar = tid >> 2;            // A loader: row 0..63
    const int ac = (tid & 3) << 2;      // A loader: k-col 0,4,8,12
    const int wr = tid >> 4;            // W loader: k-row 0..15
    const int wc = (tid & 15) << 2;     // W loader: n-col

    const float* Ap = A + (size_t)(m0 + ar) * K + ac;
    const float* Wp = W + (size_t)wr * N + n0 + wc;

    float acc[4][4] = {};

    for (int k0 = 0; k0 < K; k0 += 16) {
        float4 av = *(const float4*)(Ap + k0);
        float4 wv = *(const float4*)(Wp + (size_t)k0 * N);
        __syncthreads();
        As[ac + 0][ar] = av.x;
        As[ac + 1][ar] = av.y;
        As[ac + 2][ar] = av.z;
        As[ac + 3][ar] = av.w;
        *(float4*)&Bs[wr][wc] = wv;
        __syncthreads();
#pragma unroll
        for (int kk = 0; kk < 16; ++kk) {
            float4 a4 = *(const float4*)&As[kk][ty << 2];
            float4 b4 = *(const float4*)&Bs[kk][tx << 2];
            float aa[4] = {a4.x, a4.y, a4.z, a4.w};
            float bb[4] = {b4.x, b4.y, b4.z, b4.w};
#pragma unroll
            for (int i = 0; i < 4; ++i)
#pragma unroll
                for (int j = 0; j < 4; ++j)
                    acc[i][j] = fmaf(aa[i], bb[j], acc[i][j]);
        }
    }

    float4 bv = *(const float4*)(bias + n0 + (tx << 2));
#pragma unroll
    for (int i = 0; i < 4; ++i) {
        float4 o;
        o.x = acc[i][0] + bv.x;
        o.y = acc[i][1] + bv.y;
        o.z = acc[i][2] + bv.z;
        o.w = acc[i][3] + bv.w;
        *(float4*)(C + (size_t)(m0 + (ty << 2) + i) * N + n0 + (tx << 2)) = o;
    }
}

// ---------------- Causal flash attention, fp32 ----------------
// Block: 256 threads = 64 query rows x 4 lanes (p = tid&3).
// Per 64-key tile:
//   pass1: thread computes raw scores for keys j = 4*jj + p (full 64-dim dot,
//          q row held in registers), writes S to shared Ps, online max via
//          quartet shuffles, exp-rewrite in place, online l/m update.
//   pass2: thread accumulates output dims {c*16 + p*4 .. +3 | c=0..3} over all
//          64 keys of the tile (interleaved so float4 V reads are conflict-free).
__global__ __launch_bounds__(256, 2) void flash_kernel(
    const float* __restrict__ Qg, const float* __restrict__ Kg,
    const float* __restrict__ Vg, float* __restrict__ Og)
{
    extern __shared__ float sm[];
    float* Ks = sm;                    // [64][KVS]
    float* Vs = sm + 64 * KVS;         // [64][KVS]
    float* Ps = sm + 2 * 64 * KVS;     // [64][PSS]

    const int tid = threadIdx.x;
    const int r = tid >> 2;
    const int p = tid & 3;
    const int qt = (int)gridDim.x - 1 - (int)blockIdx.x;  // heaviest q-tiles first
    const int h = blockIdx.y;
    const int q0 = qt * 64;
    const int hc = h * HDIM;

    // q row in registers, pre-scaled by 1/sqrt(HD) = 0.125
    float q[64];
    const float* qp = Qg + (size_t)(q0 + r) * DMODEL + hc;
#pragma unroll
    for (int i = 0; i < 64; i += 4) {
        float4 v = *(const float4*)(qp + i);
        q[i]     = v.x * 0.125f;
        q[i + 1] = v.y * 0.125f;
        q[i + 2] = v.z * 0.125f;
        q[i + 3] = v.w * 0.125f;
    }

    float acc[16] = {};
    float mrow = -1e30f, lrow = 0.f;

    for (int kt = 0; kt <= qt; ++kt) {
        const int k0 = kt * 64;
        __syncthreads();  // previous tile's smem reads complete
#pragma unroll
        for (int t = 0; t < 4; ++t) {
            int idx = tid + t * 256;          // 1024 float4 slots per tensor
            int row = idx >> 4;
            int c   = (idx & 15) << 2;
            const size_t goff = (size_t)(k0 + row) * DMODEL + hc + c;
            *(float4*)&Ks[row * KVS + c] = *(const float4*)(Kg + goff);
            *(float4*)&Vs[row * KVS + c] = *(const float4*)(Vg + goff);
        }
        __syncthreads();

        // ---- pass 1: raw scores ----
        float tmax = -1e30f;
        const bool diag = (kt == qt);
#pragma unroll 1
        for (int jj = 0; jj < 16; ++jj) {
            const int j = (jj << 2) + p;
            const float* kr = Ks + j * KVS;
            float s = 0.f;
#pragma unroll
            for (int i = 0; i < 64; i += 4) {
                float4 k4 = *(const float4*)(kr + i);
                s = fmaf(q[i],     k4.x, s);
                s = fmaf(q[i + 1], k4.y, s);
                s = fmaf(q[i + 2], k4.z, s);
                s = fmaf(q[i + 3], k4.w, s);
            }
            if (diag && j > r) s = -1e30f;   // masked -> exp underflows to 0 (matches ref -1e9 in fp32)
            Ps[r * PSS + j] = s;
            tmax = fmaxf(tmax, s);
        }
        tmax = fmaxf(tmax, __shfl_xor_sync(0xffffffffu, tmax, 1));
        tmax = fmaxf(tmax, __shfl_xor_sync(0xffffffffu, tmax, 2));
        const float mnew = fmaxf(mrow, tmax);
        const float corr = __expf(mrow - mnew);
        float lsum = 0.f;
#pragma unroll 1
        for (int jj = 0; jj < 16; ++jj) {
            const int j = (jj << 2) + p;
            float e = __expf(Ps[r * PSS + j] - mnew);
            Ps[r * PSS + j] = e;
            lsum += e;
        }
        lsum += __shfl_xor_sync(0xffffffffu, lsum, 1);
        lsum += __shfl_xor_sync(0xffffffffu, lsum, 2);
        lrow = lrow * corr + lsum;
        mrow = mnew;
#pragma unroll
        for (int i = 0; i < 16; ++i) acc[i] *= corr;
        __syncthreads();  // all quartet P values visible

        // ---- pass 2: acc += P @ V ----
#pragma unroll 2
        for (int j = 0; j < 64; ++j) {
            const float pj = Ps[r * PSS + j];
            const float* vr = Vs + j * KVS + (p << 2);
#pragma unroll
            for (int c = 0; c < 4; ++c) {
                float4 v4 = *(const float4*)(vr + (c << 4));
                acc[c * 4 + 0] = fmaf(pj, v4.x, acc[c * 4 + 0]);
                acc[c * 4 + 1] = fmaf(pj, v4.y, acc[c * 4 + 1]);
                acc[c * 4 + 2] = fmaf(pj, v4.z, acc[c * 4 + 2]);
                acc[c * 4 + 3] = fmaf(pj, v4.w, acc[c * 4 + 3]);
            }
        }
    }

    const float inv = 1.f / lrow;
    float* op = Og + (size_t)(q0 + r) * DMODEL + hc + (p << 2);
#pragma unroll
    for (int c = 0; c < 4; ++c) {
        float4 o;
        o.x = acc[c * 4 + 0] * inv;
        o.y = acc[c * 4 + 1] * inv;
        o.z = acc[c * 4 + 2] * inv;
        o.w = acc[c * 4 + 3] * inv;
        *(float4*)(op + (c << 4)) = o;
    }
}

extern "C" void kernel_launch(void* const* d_in, const int* in_sizes, int n_in,
                              void* d_out, int out_size)
{
    const float* x  = (const float*)d_in[0];
    const float* Wq = (const float*)d_in[1];
    const float* bq = (const float*)d_in[2];
    const float* Wk = (const float*)d_in[3];
    const float* bk = (const float*)d_in[4];
    const float* Wv = (const float*)d_in[5];
    const float* bv = (const float*)d_in[6];
    const float* Wo = (const float*)d_in[7];
    const float* bo = (const float*)d_in[8];
    float* out = (float*)d_out;

    float* scratch = nullptr;
    cudaGetSymbolAddress((void**)&scratch, g_scratch);
    float* Qb = scratch;
    float* Kb = scratch + 1ull * SEQ * DMODEL;
    float* Vb = scratch + 2ull * SEQ * DMODEL;
    float* Ab = scratch + 3ull * SEQ * DMODEL;

    dim3 gg(DMODEL / 64, SEQ / 64);
    gemm_bias_kernel<<<gg, 256>>>(x, Wq, bq, Qb, SEQ, DMODEL, DMODEL);
    gemm_bias_kernel<<<gg, 256>>>(x, Wk, bk, Kb, SEQ, DMODEL, DMODEL);
    gemm_bias_kernel<<<gg, 256>>>(x, Wv, bv, Vb, SEQ, DMODEL, DMODEL);

    const int smem = (2 * 64 * KVS + 64 * PSS) * (int)sizeof(float);  // 51456 B
    cudaFuncSetAttribute(flash_kernel, cudaFuncAttributeMaxDynamicSharedMemorySize, smem);
    flash_kernel<<<dim3(SEQ / 64, NH), 256, smem>>>(Qb, Kb, Vb, Ab);

    gemm_bias_kernel<<<gg, 256>>>(Ab, Wo, bo, out, SEQ, DMODEL, DMODEL);
}

// round 5
// speedup vs baseline: 1.0093x; 1.0093x over previous
#include <cuda_runtime.h>

#define SEQ     4096
#define DMODEL  1024
#define NH      16
#define HDIM    64
#define KVS     68   // Ks/Vs row stride (floats): 68%32=4 -> consecutive rows hit distinct bank quads
#define PSS     65   // Ps row stride

// Scratch: Q, K, V, AttnOut  (4 x 16 MB fp32)
__device__ float g_scratch[4ull * SEQ * DMODEL];

// ---------------- GEMM: C[M,N] = A[M,K] @ W[K,N] + bias[N] ----------------
__global__ __launch_bounds__(256) void gemm_bias_kernel(
    const float* __restrict__ A, const float* __restrict__ W,
    const float* __restrict__ bias, float* __restrict__ C,
    int M, int N, int K)
{
    __shared__ float As[16][64];   // transposed: As[k][m]
    __shared__ float Bs[16][64];   // Bs[k][n]
    const int tid = threadIdx.x;
    const int n0 = blockIdx.x * 64;
    const int m0 = blockIdx.y * 64;
    const int tx = tid & 15;
    const int ty = tid >> 4;

    const int ar = tid >> 2;            // A loader: row 0..63
    const int ac = (tid & 3) << 2;      // A loader: k-col 0,4,8,12
    const int wr = tid >> 4;            // W loader: k-row 0..15
    const int wc = (tid & 15) << 2;     // W loader: n-col

    const float* Ap = A + (size_t)(m0 + ar) * K + ac;
    const float* Wp = W + (size_t)wr * N + n0 + wc;

    float acc[4][4] = {};

    for (int k0 = 0; k0 < K; k0 += 16) {
        float4 av = *(const float4*)(Ap + k0);
        float4 wv = *(const float4*)(Wp + (size_t)k0 * N);
        __syncthreads();
        As[ac + 0][ar] = av.x;
        As[ac + 1][ar] = av.y;
        As[ac + 2][ar] = av.z;
        As[ac + 3][ar] = av.w;
        *(float4*)&Bs[wr][wc] = wv;
        __syncthreads();
#pragma unroll
        for (int kk = 0; kk < 16; ++kk) {
            float4 a4 = *(const float4*)&As[kk][ty << 2];
            float4 b4 = *(const float4*)&Bs[kk][tx << 2];
            float aa[4] = {a4.x, a4.y, a4.z, a4.w};
            float bb[4] = {b4.x, b4.y, b4.z, b4.w};
#pragma unroll
            for (int i = 0; i < 4; ++i)
#pragma unroll
                for (int j = 0; j < 4; ++j)
                    acc[i][j] = fmaf(aa[i], bb[j], acc[i][j]);
        }
    }

    float4 bv = *(const float4*)(bias + n0 + (tx << 2));
#pragma unroll
    for (int i = 0; i < 4; ++i) {
        float4 o;
        o.x = acc[i][0] + bv.x;
        o.y = acc[i][1] + bv.y;
        o.z = acc[i][2] + bv.z;
        o.w = acc[i][3] + bv.w;
        *(float4*)(C + (size_t)(m0 + (ty << 2) + i) * N + n0 + (tx << 2)) = o;
    }
}

// ---------------- Causal flash attention, fp32 ----------------
// Block: 256 threads = 64 query rows x 4 lanes (p = tid&3).
// Per 64-key tile:
//   pass1: thread computes raw scores for keys j = 4*jj + p (full 64-dim dot,
//          q row held in registers), writes S to shared Ps, online max via
//          quartet shuffles, exp-rewrite in place, online l/m update.
//   pass2: thread accumulates output dims {c*16 + p*4 .. +3 | c=0..3} over all
//          64 keys of the tile (interleaved so float4 V reads are conflict-free).
__global__ __launch_bounds__(256, 2) void flash_kernel(
    const float* __restrict__ Qg, const float* __restrict__ Kg,
    const float* __restrict__ Vg, float* __restrict__ Og)
{
    extern __shared__ float sm[];
    float* Ks = sm;                    // [64][KVS]
    float* Vs = sm + 64 * KVS;         // [64][KVS]
    float* Ps = sm + 2 * 64 * KVS;     // [64][PSS]

    const int tid = threadIdx.x;
    const int r = tid >> 2;
    const int p = tid & 3;
    const int qt = (int)gridDim.x - 1 - (int)blockIdx.x;  // heaviest q-tiles first
    const int h = blockIdx.y;
    const int q0 = qt * 64;
    const int hc = h * HDIM;

    // q row in registers, pre-scaled by 1/sqrt(HD) = 0.125
    float q[64];
    const float* qp = Qg + (size_t)(q0 + r) * DMODEL + hc;
#pragma unroll
    for (int i = 0; i < 64; i += 4) {
        float4 v = *(const float4*)(qp + i);
        q[i]     = v.x * 0.125f;
        q[i + 1] = v.y * 0.125f;
        q[i + 2] = v.z * 0.125f;
        q[i + 3] = v.w * 0.125f;
    }

    float acc[16] = {};
    float mrow = -1e30f, lrow = 0.f;

    for (int kt = 0; kt <= qt; ++kt) {
        const int k0 = kt * 64;
        __syncthreads();  // previous tile's smem reads complete
#pragma unroll
        for (int t = 0; t < 4; ++t) {
            int idx = tid + t * 256;          // 1024 float4 slots per tensor
            int row = idx >> 4;
            int c   = (idx & 15) << 2;
            const size_t goff = (size_t)(k0 + row) * DMODEL + hc + c;
            *(float4*)&Ks[row * KVS + c] = *(const float4*)(Kg + goff);
            *(float4*)&Vs[row * KVS + c] = *(const float4*)(Vg + goff);
        }
        __syncthreads();

        // ---- pass 1: raw scores ----
        float tmax = -1e30f;
        const bool diag = (kt == qt);
#pragma unroll 1
        for (int jj = 0; jj < 16; ++jj) {
            const int j = (jj << 2) + p;
            const float* kr = Ks + j * KVS;
            float s = 0.f;
#pragma unroll
            for (int i = 0; i < 64; i += 4) {
                float4 k4 = *(const float4*)(kr + i);
                s = fmaf(q[i],     k4.x, s);
                s = fmaf(q[i + 1], k4.y, s);
                s = fmaf(q[i + 2], k4.z, s);
                s = fmaf(q[i + 3], k4.w, s);
            }
            if (diag && j > r) s = -1e30f;   // masked -> exp underflows to 0 (matches ref -1e9 in fp32)
            Ps[r * PSS + j] = s;
            tmax = fmaxf(tmax, s);
        }
        tmax = fmaxf(tmax, __shfl_xor_sync(0xffffffffu, tmax, 1));
        tmax = fmaxf(tmax, __shfl_xor_sync(0xffffffffu, tmax, 2));
        const float mnew = fmaxf(mrow, tmax);
        const float corr = __expf(mrow - mnew);
        float lsum = 0.f;
#pragma unroll 1
        for (int jj = 0; jj < 16; ++jj) {
            const int j = (jj << 2) + p;
            float e = __expf(Ps[r * PSS + j] - mnew);
            Ps[r * PSS + j] = e;
            lsum += e;
        }
        lsum += __shfl_xor_sync(0xffffffffu, lsum, 1);
        lsum += __shfl_xor_sync(0xffffffffu, lsum, 2);
        lrow = lrow * corr + lsum;
        mrow = mnew;
#pragma unroll
        for (int i = 0; i < 16; ++i) acc[i] *= corr;
        __syncthreads();  // all quartet P values visible

        // ---- pass 2: acc += P @ V ----
#pragma unroll 2
        for (int j = 0; j < 64; ++j) {
            const float pj = Ps[r * PSS + j];
            const float* vr = Vs + j * KVS + (p << 2);
#pragma unroll
            for (int c = 0; c < 4; ++c) {
                float4 v4 = *(const float4*)(vr + (c << 4));
                acc[c * 4 + 0] = fmaf(pj, v4.x, acc[c * 4 + 0]);
                acc[c * 4 + 1] = fmaf(pj, v4.y, acc[c * 4 + 1]);
                acc[c * 4 + 2] = fmaf(pj, v4.z, acc[c * 4 + 2]);
                acc[c * 4 + 3] = fmaf(pj, v4.w, acc[c * 4 + 3]);
            }
        }
    }

    const float inv = 1.f / lrow;
    float* op = Og + (size_t)(q0 + r) * DMODEL + hc + (p << 2);
#pragma unroll
    for (int c = 0; c < 4; ++c) {
        float4 o;
        o.x = acc[c * 4 + 0] * inv;
        o.y = acc[c * 4 + 1] * inv;
        o.z = acc[c * 4 + 2] * inv;
        o.w = acc[c * 4 + 3] * inv;
        *(float4*)(op + (c << 4)) = o;
    }
}

extern "C" void kernel_launch(void* const* d_in, const int* in_sizes, int n_in,
                              void* d_out, int out_size)
{
    const float* x  = (const float*)d_in[0];
    const float* Wq = (const float*)d_in[1];
    const float* bq = (const float*)d_in[2];
    const float* Wk = (const float*)d_in[3];
    const float* bk = (const float*)d_in[4];
    const float* Wv = (const float*)d_in[5];
    const float* bv = (const float*)d_in[6];
    const float* Wo = (const float*)d_in[7];
    const float* bo = (const float*)d_in[8];
    float* out = (float*)d_out;

    float* scratch = nullptr;
    cudaGetSymbolAddress((void**)&scratch, g_scratch);
    float* Qb = scratch;
    float* Kb = scratch + 1ull * SEQ * DMODEL;
    float* Vb = scratch + 2ull * SEQ * DMODEL;
    float* Ab = scratch + 3ull * SEQ * DMODEL;

    dim3 gg(DMODEL / 64, SEQ / 64);
    gemm_bias_kernel<<<gg, 256>>>(x, Wq, bq, Qb, SEQ, DMODEL, DMODEL);
    gemm_bias_kernel<<<gg, 256>>>(x, Wk, bk, Kb, SEQ, DMODEL, DMODEL);
    gemm_bias_kernel<<<gg, 256>>>(x, Wv, bv, Vb, SEQ, DMODEL, DMODEL);

    const int smem = (2 * 64 * KVS + 64 * PSS) * (int)sizeof(float);  // 51456 B
    cudaFuncSetAttribute(flash_kernel, cudaFuncAttributeMaxDynamicSharedMemorySize, smem);
    flash_kernel<<<dim3(SEQ / 64, NH), 256, smem>>>(Qb, Kb, Vb, Ab);

    gemm_bias_kernel<<<gg, 256>>>(Ab, Wo, bo, out, SEQ, DMODEL, DMODEL);
}